// round 6
// baseline (speedup 1.0000x reference)
#include <cuda_runtime.h>
#include <math_constants.h>
#include <stdint.h>

#define NB    8
#define NPTS  4096
#define KNN   20
#define CH    64
#define NSAMP (NB*NPTS*KNN)      // 655360
#define NQ    (NB*NPTS)          // 32768 queries
#define NSEG  2
#define SEGN  (NPTS/NSEG)        // 2048
#define BN_EPS 1e-5
#define SLOPE  0.2f

// ---------------- device scratch ----------------
__device__ float4 g_packed[NB*NPTS];                 // (x,y,z,|p|^2)
__device__ float  g_E8[(size_t)NSAMP*8];             // edge feats padded to 8
__device__ float  g_dl[NSEG*NQ*KNN];                 // per-segment sorted dists
__device__ double g_S1[6];
__device__ double g_S2[21];
__device__ float  g_W1f[CH*6];
__device__ float  g_c1[CH];
__device__ double g_h2sum[CH];
__device__ double g_h2sq[CH];
__device__ float  g_a2[CH], g_c2[CH];
__device__ float  g_hmax[(size_t)NB*NPTS*CH];
__device__ float  g_hmin[(size_t)NB*NPTS*CH];

// ---------------- packed f32x2 helpers ----------------
__device__ __forceinline__ unsigned long long fma2(unsigned long long a,
                                                   unsigned long long b,
                                                   unsigned long long c) {
    unsigned long long d;
    asm("fma.rn.f32x2 %0, %1, %2, %3;" : "=l"(d) : "l"(a), "l"(b), "l"(c));
    return d;
}
__device__ __forceinline__ unsigned long long pack2(float x) {
    unsigned long long d;
    asm("mov.b64 %0, {%1, %1};" : "=l"(d) : "f"(x));
    return d;
}
__device__ __forceinline__ void unpack2(unsigned long long v, float& lo, float& hi) {
    asm("mov.b64 {%0, %1}, %2;" : "=f"(lo), "=f"(hi) : "l"(v));
}

// ---------------- dummy (ncu lands on launch index 3 -> k1_seg) --------
__global__ void kdummy() {}

// ---------------- K0: pack points + zero accumulators ----------------
__global__ void k0_pack(const float* __restrict__ a) {
    int t = blockIdx.x*blockDim.x + threadIdx.x;     // 0..32767
    int b = t / NPTS, n = t % NPTS;
    const float* ab = a + (size_t)b*3*NPTS;
    float x = ab[n], y = ab[NPTS+n], z = ab[2*NPTS+n];
    float sq = fmaf(z,z, fmaf(y,y, x*x));
    g_packed[t] = make_float4(x,y,z,sq);
    if (blockIdx.x == 0) {
        int i = threadIdx.x;
        if (i < 6)  g_S1[i] = 0.0;
        if (i < 21) g_S2[i] = 0.0;
        if (i < CH) { g_h2sum[i] = 0.0; g_h2sq[i] = 0.0; }
    }
}

// ---------------- K1a: segmented distance-only top-20 ------------------
// d' = sq_j - 2*dot(p_i,p_j). Branchless sorted-insert network:
//   dl[t] = min(dl[t], max(d, dl[t-1]))   (exact, 2 FMNMX/slot, no preds)
// Produces the exact multiset of the 20 smallest d' per segment, sorted.
__global__ void __launch_bounds__(128) k1_seg() {
    int blk = blockIdx.x;                            // 0..511
    int seg = (blk >= 256) ? 1 : 0;
    int qid = (blk & 255)*128 + threadIdx.x;         // 0..32767
    int b = qid / NPTS; int i = qid % NPTS;
    const float4* pts = &g_packed[b*NPTS];
    float4 pi = pts[i];
    float n2x = -2.f*pi.x, n2y = -2.f*pi.y, n2z = -2.f*pi.z;

    float dl[KNN];
    #pragma unroll
    for (int t = 0; t < KNN; t++) dl[t] = CUDART_INF_F;

    int jbase = seg * SEGN;
    for (int j = 0; j < SEGN; j += 8) {
        float dd[8];
        #pragma unroll
        for (int u = 0; u < 8; u++) {
            float4 pj = __ldg(&pts[jbase + j + u]);
            dd[u] = fmaf(n2z, pj.z, fmaf(n2y, pj.y, fmaf(n2x, pj.x, pj.w)));
        }
        #pragma unroll
        for (int u = 0; u < 8; u++) {
            float d = dd[u];
            if (d < dl[KNN-1]) {
                #pragma unroll
                for (int t = KNN-1; t >= 1; t--)
                    dl[t] = fminf(dl[t], fmaxf(d, dl[t-1]));
                dl[0] = fminf(dl[0], d);
            }
        }
    }
    size_t o = ((size_t)seg*NQ + qid)*KNN;
    #pragma unroll
    for (int t = 0; t < KNN; t++) g_dl[o+t] = dl[t];
}

// ---------------- K1b: threshold rescan + emit edge features -----------
// thr = 20th smallest over both segment lists (merged inline).
// Emit all j with d < thr, then first (20 - m) ties d == thr in j order.
// Exact top-20 SET; k-order is irrelevant downstream. Identical fmaf
// chains in both passes make the == comparison bitwise-sound.
__device__ __forceinline__ void emitE(float4* E, int slot, float4 pj, float4 pi) {
    E[slot*2+0] = make_float4(pj.x-pi.x, pj.y-pi.y, pj.z-pi.z, pi.x);
    E[slot*2+1] = make_float4(pi.y, pi.z, 0.f, 0.f);
}
__global__ void __launch_bounds__(256) k1_emit() {
    int qid = blockIdx.x*blockDim.x + threadIdx.x;   // 0..32767
    int b = qid / NPTS; int i = qid % NPTS;
    const float4* pts = &g_packed[b*NPTS];
    float4 pi = pts[i];
    float n2x = -2.f*pi.x, n2y = -2.f*pi.y, n2z = -2.f*pi.z;

    // merge the two sorted 20-lists to find the 20th smallest value
    const float* A = &g_dl[(size_t)qid*KNN];
    const float* B = &g_dl[((size_t)NQ + qid)*KNN];
    float thr = 0.f;
    {
        int ia = 0, ib = 0;
        float da = A[0], db = B[0];
        #pragma unroll
        for (int t = 0; t < KNN; t++) {
            bool ta = (da <= db);
            thr = ta ? da : db;
            if (ta) { ia++; da = (ia < KNN) ? A[ia] : CUDART_INF_F; }
            else    { ib++; db = (ib < KNN) ? B[ib] : CUDART_INF_F; }
        }
    }

    float4* E = (float4*)(g_E8 + (size_t)qid*KNN*8);
    int ml = 0, T = 0;
    int t0 = 0, t1 = 0, t2 = 0, t3 = 0;
    for (int j = 0; j < NPTS; j += 8) {
        float dd[8];
        #pragma unroll
        for (int u = 0; u < 8; u++) {
            float4 pj = __ldg(&pts[j+u]);
            dd[u] = fmaf(n2z, pj.z, fmaf(n2y, pj.y, fmaf(n2x, pj.x, pj.w)));
        }
        #pragma unroll
        for (int u = 0; u < 8; u++) {
            float d = dd[u];
            if (d <= thr) {
                int jj = j + u;
                if (d < thr) { emitE(E, ml, pts[jj], pi); ml++; }
                else {
                    if      (T == 0) t0 = jj;
                    else if (T == 1) t1 = jj;
                    else if (T == 2) t2 = jj;
                    else if (T == 3) t3 = jj;
                    T++;
                }
            }
        }
    }
    int need = KNN - ml;                 // >= 1 always (boundary element)
    if (need >= 1 && T >= 1) { emitE(E, ml, pts[t0], pi); ml++; }
    if (need >= 2 && T >= 2) { emitE(E, ml, pts[t1], pi); ml++; }
    if (need >= 3 && T >= 3) { emitE(E, ml, pts[t2], pi); ml++; }
    if (need >= 4 && T >= 4) { emitE(E, ml, pts[t3], pi); ml++; }
    if (ml < KNN) {                      // pathological >4-way tie: rescan
        int skip = 4;
        for (int j = 0; j < NPTS && ml < KNN; j++) {
            float4 pj = __ldg(&pts[j]);
            float d = fmaf(n2z, pj.z, fmaf(n2y, pj.y, fmaf(n2x, pj.x, pj.w)));
            if (d == thr) {
                if (skip > 0) skip--;
                else { emitE(E, ml, pj, pi); ml++; }
            }
        }
    }
}

// ---------------- K2: 1st+2nd moments of edge features ----------------
__global__ void k2_mom() {
    int t = blockIdx.x*blockDim.x + threadIdx.x;     // 512x256 -> 5 samples each
    float s1[6]; float s2[21];
    #pragma unroll
    for (int c = 0; c < 6; c++)  s1[c] = 0.f;
    #pragma unroll
    for (int q = 0; q < 21; q++) s2[q] = 0.f;

    #pragma unroll
    for (int s = 0; s < 5; s++) {
        size_t idx = (size_t)(t*5 + s) * 8;
        float4 v0 = *(const float4*)&g_E8[idx];
        float4 v1 = *(const float4*)&g_E8[idx+4];
        float x[6] = {v0.x, v0.y, v0.z, v0.w, v1.x, v1.y};
        #pragma unroll
        for (int c = 0; c < 6; c++) s1[c] += x[c];
        int q = 0;
        #pragma unroll
        for (int c1 = 0; c1 < 6; c1++)
            #pragma unroll
            for (int c2 = c1; c2 < 6; c2++) { s2[q] = fmaf(x[c1], x[c2], s2[q]); q++; }
    }
    #pragma unroll
    for (int o = 16; o > 0; o >>= 1) {
        #pragma unroll
        for (int c = 0; c < 6; c++)  s1[c] += __shfl_xor_sync(~0u, s1[c], o);
        #pragma unroll
        for (int q = 0; q < 21; q++) s2[q] += __shfl_xor_sync(~0u, s2[q], o);
    }
    if ((threadIdx.x & 31) == 0) {
        #pragma unroll
        for (int c = 0; c < 6; c++)  atomicAdd(&g_S1[c], (double)s1[c]);
        #pragma unroll
        for (int q = 0; q < 21; q++) atomicAdd(&g_S2[q], (double)s2[q]);
    }
}

// ---------------- F1: fold BN1 into W1 ----------------
__global__ void f1_fold(const float* __restrict__ W1, const float* __restrict__ g1,
                        const float* __restrict__ b1) {
    int o = threadIdx.x; if (o >= CH) return;
    double M = (double)NSAMP;
    double m1[6];
    for (int c = 0; c < 6; c++) m1[c] = g_S1[c] / M;
    double E2[6][6]; int q = 0;
    for (int c1 = 0; c1 < 6; c1++)
        for (int c2 = c1; c2 < 6; c2++) { double v = g_S2[q++] / M; E2[c1][c2] = v; E2[c2][c1] = v; }
    double w[6];
    for (int c = 0; c < 6; c++) w[c] = (double)W1[o*6 + c];
    double mean = 0.0;
    for (int c = 0; c < 6; c++) mean += w[c]*m1[c];
    double e2 = 0.0;
    for (int c1 = 0; c1 < 6; c1++) { double acc = 0.0;
        for (int c2 = 0; c2 < 6; c2++) acc += w[c2]*E2[c1][c2];
        e2 += w[c1]*acc; }
    double var = e2 - mean*mean;
    double a = (double)g1[o] / sqrt(var + BN_EPS);
    g_c1[o] = (float)((double)b1[o] - mean*a);
    for (int c = 0; c < 6; c++) g_W1f[o*6 + c] = (float)(a*w[c]);
}

// ---------------- K3: fused MLP (f32x2 packed), BN2 stats, max/min over K
#define YPITCH 22
__global__ void __launch_bounds__(256) k3_mlp(const float* __restrict__ W2) {
    __shared__ float sW2T[CH*CH];          // [c][u]
    __shared__ float y1s[4][CH*YPITCH];    // [p][c*22 + k]
    __shared__ float smx[4][CH], smn[4][CH];
    __shared__ float ssum[CH], ssq[CH];
    int t = threadIdx.x;
    if (t < CH) { ssum[t] = 0.f; ssq[t] = 0.f; }
    for (int s = t; s < CH*CH; s += 256) { int o = s >> 6, c = s & 63; sW2T[c*CH + o] = W2[s]; }

    int pa = t >> 6, ca = t & 63;
    float w1r[6];
    #pragma unroll
    for (int c = 0; c < 6; c++) w1r[c] = g_W1f[ca*6 + c];
    float c1v = g_c1[ca];

    int r  = t & 63;
    int kq = r >> 5;
    int ug = r & 31;
    int u0 = 2*ug, u1 = u0 + 1;
    int k0 = kq * 10;
    float su0 = 0.f, su1 = 0.f, qu0 = 0.f, qu1 = 0.f;
    __syncthreads();

    for (int ph = 0; ph < 4; ph++) {
        int pbase = blockIdx.x*16 + ph*4;
        {
            const float* Ep = g_E8 + (size_t)(pbase + pa)*KNN*8;
            float* yo = &y1s[pa][ca*YPITCH];
            #pragma unroll
            for (int k = 0; k < KNN; k++) {
                float4 v0 = *(const float4*)(Ep + k*8);
                float4 v1 = *(const float4*)(Ep + k*8 + 4);
                float h = c1v;
                h = fmaf(w1r[0], v0.x, h);
                h = fmaf(w1r[1], v0.y, h);
                h = fmaf(w1r[2], v0.z, h);
                h = fmaf(w1r[3], v0.w, h);
                h = fmaf(w1r[4], v1.x, h);
                h = fmaf(w1r[5], v1.y, h);
                yo[k] = (h >= 0.f) ? h : SLOPE*h;
            }
        }
        __syncthreads();
        unsigned long long acc0[5], acc1[5];
        #pragma unroll
        for (int kk = 0; kk < 5; kk++) { acc0[kk] = 0ull; acc1[kk] = 0ull; }
        const float* yb = &y1s[pa][0];
        #pragma unroll 8
        for (int c = 0; c < CH; c++) {
            float2 wp = *(const float2*)&sW2T[c*CH + u0];
            unsigned long long w0d = pack2(wp.x);
            unsigned long long w1d = pack2(wp.y);
            const float* yr = yb + c*YPITCH + k0;
            #pragma unroll
            for (int kk = 0; kk < 5; kk++) {
                unsigned long long yv = *(const unsigned long long*)(yr + 2*kk);
                acc0[kk] = fma2(w0d, yv, acc0[kk]);
                acc1[kk] = fma2(w1d, yv, acc1[kk]);
            }
        }
        float mx0 = -CUDART_INF_F, mn0 = CUDART_INF_F;
        float mx1 = -CUDART_INF_F, mn1 = CUDART_INF_F;
        #pragma unroll
        for (int kk = 0; kk < 5; kk++) {
            float lo, hi;
            unpack2(acc0[kk], lo, hi);
            su0 += lo + hi; qu0 = fmaf(lo, lo, fmaf(hi, hi, qu0));
            mx0 = fmaxf(mx0, fmaxf(lo, hi)); mn0 = fminf(mn0, fminf(lo, hi));
            unpack2(acc1[kk], lo, hi);
            su1 += lo + hi; qu1 = fmaf(lo, lo, fmaf(hi, hi, qu1));
            mx1 = fmaxf(mx1, fmaxf(lo, hi)); mn1 = fminf(mn1, fminf(lo, hi));
        }
        if (kq == 1) {
            smx[pa][u0] = mx0; smx[pa][u1] = mx1;
            smn[pa][u0] = mn0; smn[pa][u1] = mn1;
        }
        __syncthreads();
        if (kq == 0) {
            size_t o = (size_t)(pbase + pa)*CH;
            g_hmax[o + u0] = fmaxf(mx0, smx[pa][u0]);
            g_hmax[o + u1] = fmaxf(mx1, smx[pa][u1]);
            g_hmin[o + u0] = fminf(mn0, smn[pa][u0]);
            g_hmin[o + u1] = fminf(mn1, smn[pa][u1]);
        }
        __syncthreads();
    }
    atomicAdd(&ssum[u0], su0); atomicAdd(&ssum[u1], su1);
    atomicAdd(&ssq[u0],  qu0); atomicAdd(&ssq[u1],  qu1);
    __syncthreads();
    if (t < CH) {
        atomicAdd(&g_h2sum[t], (double)ssum[t]);
        atomicAdd(&g_h2sq[t],  (double)ssq[t]);
    }
}

// ---------------- F2: finalize BN2 ----------------
__global__ void f2_fold(const float* __restrict__ g2, const float* __restrict__ b2) {
    int o = threadIdx.x; if (o >= CH) return;
    double M = (double)NSAMP;
    double m = g_h2sum[o] / M;
    double v = g_h2sq[o] / M - m*m;
    double a = (double)g2[o] / sqrt(v + BN_EPS);
    g_a2[o] = (float)a;
    g_c2[o] = (float)((double)b2[o] - m*a);
}

// ---------------- K5: BN2+lrelu via monotone max/min + transpose -------
__global__ void k5_out(float* __restrict__ out) {
    __shared__ float tile[32][33];
    int b = blockIdx.z;
    int n0 = blockIdx.x*32, o0 = blockIdx.y*32;
    int tx = threadIdx.x, ty = threadIdx.y;
    #pragma unroll
    for (int r = 0; r < 4; r++) {
        int n = n0 + ty + 8*r, o = o0 + tx;
        float a = g_a2[o], c = g_c2[o];
        size_t idx = ((size_t)(b*NPTS + n))*CH + o;
        float h = (a >= 0.f) ? g_hmax[idx] : g_hmin[idx];
        float v = fmaf(a, h, c);
        tile[ty + 8*r][tx] = (v >= 0.f) ? v : SLOPE*v;
    }
    __syncthreads();
    #pragma unroll
    for (int r = 0; r < 4; r++) {
        int o = o0 + ty + 8*r, n = n0 + tx;
        out[((size_t)(b*CH + o))*NPTS + n] = tile[tx][ty + 8*r];
    }
}

// ---------------- launch ----------------
extern "C" void kernel_launch(void* const* d_in, const int* in_sizes, int n_in,
                              void* d_out, int out_size) {
    const float* a  = (const float*)d_in[0];
    const float* W1 = (const float*)d_in[1];
    const float* g1 = (const float*)d_in[2];
    const float* b1 = (const float*)d_in[3];
    const float* W2 = (const float*)d_in[4];
    const float* g2 = (const float*)d_in[5];
    const float* b2 = (const float*)d_in[6];
    float* out = (float*)d_out;

    // 2 dummies: ncu capture lands on launch index 3 == k1_seg
    kdummy<<<1, 32>>>();
    kdummy<<<1, 32>>>();

    k0_pack<<<128, 256>>>(a);        // index 2
    k1_seg<<<512, 128>>>();          // index 3  <- profiled
    k1_emit<<<128, 256>>>();
    k2_mom<<<512, 256>>>();
    f1_fold<<<1, 64>>>(W1, g1, b1);
    k3_mlp<<<2048, 256>>>(W2);
    f2_fold<<<1, 64>>>(g2, b2);
    k5_out<<<dim3(128, 2, NB), dim3(32, 8)>>>(out);
}

// round 7
// speedup vs baseline: 1.2516x; 1.2516x over previous
#include <cuda_runtime.h>
#include <math_constants.h>
#include <stdint.h>

#define NB    8
#define NPTS  4096
#define KNN   20
#define CH    64
#define NSAMP (NB*NPTS*KNN)      // 655360
#define NQ    (NB*NPTS)          // 32768 queries
#define NSEG  2
#define SEGN  (NPTS/NSEG)        // 2048
#define BN_EPS 1e-5
#define SLOPE  0.2f

// ---------------- device scratch ----------------
__device__ float4 g_packed[NB*NPTS];                 // (x,y,z,|p|^2)
__device__ float  g_E8[(size_t)NSAMP*8];             // edge feats padded to 8
__device__ float  g_dl[NSEG*NQ*KNN];                 // per-segment sorted dists
__device__ double g_S1[6];
__device__ double g_S2[21];
__device__ float  g_W1f[CH*6];
__device__ float  g_c1[CH];
__device__ double g_h2sum[CH];
__device__ double g_h2sq[CH];
__device__ float  g_a2[CH], g_c2[CH];
__device__ float  g_hmax[(size_t)NB*NPTS*CH];
__device__ float  g_hmin[(size_t)NB*NPTS*CH];

// ---------------- packed f32x2 helpers ----------------
__device__ __forceinline__ unsigned long long fma2(unsigned long long a,
                                                   unsigned long long b,
                                                   unsigned long long c) {
    unsigned long long d;
    asm("fma.rn.f32x2 %0, %1, %2, %3;" : "=l"(d) : "l"(a), "l"(b), "l"(c));
    return d;
}
__device__ __forceinline__ unsigned long long pack2(float x) {
    unsigned long long d;
    asm("mov.b64 %0, {%1, %1};" : "=l"(d) : "f"(x));
    return d;
}
__device__ __forceinline__ void unpack2(unsigned long long v, float& lo, float& hi) {
    asm("mov.b64 {%0, %1}, %2;" : "=f"(lo), "=f"(hi) : "l"(v));
}

// ---------------- dummy (ncu lands on launch index 3 -> k1_emit) -------
__global__ void kdummy() {}

// ---------------- K0: pack points + zero accumulators ----------------
__global__ void k0_pack(const float* __restrict__ a) {
    int t = blockIdx.x*blockDim.x + threadIdx.x;     // 0..32767
    int b = t / NPTS, n = t % NPTS;
    const float* ab = a + (size_t)b*3*NPTS;
    float x = ab[n], y = ab[NPTS+n], z = ab[2*NPTS+n];
    float sq = fmaf(z,z, fmaf(y,y, x*x));
    g_packed[t] = make_float4(x,y,z,sq);
    if (blockIdx.x == 0) {
        int i = threadIdx.x;
        if (i < 6)  g_S1[i] = 0.0;
        if (i < 21) g_S2[i] = 0.0;
        if (i < CH) { g_h2sum[i] = 0.0; g_h2sq[i] = 0.0; }
    }
}

// ---------------- K1a: segmented distance-only top-20 ------------------
// d' = sq_j - 2*dot(p_i,p_j). Branchless sorted-insert network:
//   dl[t] = min(dl[t], max(d, dl[t-1]))   (exact, 2 FMNMX/slot, no preds)
// Produces the exact multiset of the 20 smallest d' per segment, sorted.
__global__ void __launch_bounds__(128) k1_seg() {
    int blk = blockIdx.x;                            // 0..511
    int seg = (blk >= 256) ? 1 : 0;
    int qid = (blk & 255)*128 + threadIdx.x;         // 0..32767
    int b = qid / NPTS; int i = qid % NPTS;
    const float4* pts = &g_packed[b*NPTS];
    float4 pi = pts[i];
    float n2x = -2.f*pi.x, n2y = -2.f*pi.y, n2z = -2.f*pi.z;

    float dl[KNN];
    #pragma unroll
    for (int t = 0; t < KNN; t++) dl[t] = CUDART_INF_F;

    int jbase = seg * SEGN;
    for (int j = 0; j < SEGN; j += 8) {
        float dd[8];
        #pragma unroll
        for (int u = 0; u < 8; u++) {
            float4 pj = __ldg(&pts[jbase + j + u]);
            dd[u] = fmaf(n2z, pj.z, fmaf(n2y, pj.y, fmaf(n2x, pj.x, pj.w)));
        }
        #pragma unroll
        for (int u = 0; u < 8; u++) {
            float d = dd[u];
            if (d < dl[KNN-1]) {
                #pragma unroll
                for (int t = KNN-1; t >= 1; t--)
                    dl[t] = fminf(dl[t], fmaxf(d, dl[t-1]));
                dl[0] = fminf(dl[0], d);
            }
        }
    }
    size_t o = ((size_t)seg*NQ + qid)*KNN;
    #pragma unroll
    for (int t = 0; t < KNN; t++) g_dl[o+t] = dl[t];
}

// ---------------- K1b: warp-cooperative threshold rescan + emit --------
// One query per warp. 32 lanes scan 32 consecutive j per iteration
// (lane order == j order). Ballot-compacted parallel emission.
// thr = exact 20th smallest (merged from the two sorted segment lists);
// identical fmaf chains in both passes make </== bitwise-sound.
// m strict hits (<= 19) + first (20-m) ties in ascending j = exact
// lex-(d,j) top-20 SET (k-order is irrelevant downstream).
__device__ __forceinline__ void emitE(float4* E, int slot, float4 pj, float4 pi) {
    E[slot*2+0] = make_float4(pj.x-pi.x, pj.y-pi.y, pj.z-pi.z, pi.x);
    E[slot*2+1] = make_float4(pi.y, pi.z, 0.f, 0.f);
}
__global__ void __launch_bounds__(256) k1_emit() {
    __shared__ int ties[8][KNN];
    int wid  = threadIdx.x >> 5;                     // warp in block
    int lane = threadIdx.x & 31;
    int qid  = blockIdx.x*8 + wid;                   // 0..32767 (one query/warp)
    int b = qid / NPTS; int i = qid % NPTS;
    const float4* pts = &g_packed[b*NPTS];
    float4 pi = pts[i];
    float n2x = -2.f*pi.x, n2y = -2.f*pi.y, n2z = -2.f*pi.z;

    // lane 0: merge the two sorted 20-lists -> 20th smallest; broadcast
    float thr = 0.f;
    if (lane == 0) {
        const float* A = &g_dl[(size_t)qid*KNN];
        const float* B = &g_dl[((size_t)NQ + qid)*KNN];
        int ia = 0, ib = 0;
        float da = A[0], db = B[0];
        #pragma unroll
        for (int t = 0; t < KNN; t++) {
            bool ta = (da <= db);
            thr = ta ? da : db;
            if (ta) { ia++; da = (ia < KNN) ? A[ia] : CUDART_INF_F; }
            else    { ib++; db = (ib < KNN) ? B[ib] : CUDART_INF_F; }
        }
    }
    thr = __shfl_sync(~0u, thr, 0);

    float4* E = (float4*)(g_E8 + (size_t)qid*KNN*8);
    int m = 0, tcnt = 0;
    float4 pj = __ldg(&pts[lane]);                   // prefetch
    for (int it = 0; it < NPTS/32; it++) {
        float4 cur = pj;
        if (it < NPTS/32 - 1) pj = __ldg(&pts[(it+1)*32 + lane]);
        float d = fmaf(n2z, cur.z, fmaf(n2y, cur.y, fmaf(n2x, cur.x, cur.w)));
        unsigned lt = __ballot_sync(~0u, d <  thr);
        unsigned eq = __ballot_sync(~0u, d == thr);
        if (lt | eq) {
            unsigned below = (1u << lane) - 1u;
            if (d < thr)  emitE(E, m + __popc(lt & below), cur, pi);
            if (d == thr) {
                int pos = tcnt + __popc(eq & below);
                if (pos < KNN) ties[wid][pos] = it*32 + lane;
            }
            m    += __popc(lt);
            tcnt += __popc(eq);
        }
    }
    __syncwarp();
    int need = KNN - m;                              // >= 1, and tcnt >= need
    if (lane < need) {
        float4 pt = pts[ties[wid][lane]];
        emitE(E, m + lane, pt, pi);
    }
}

// ---------------- K2: 1st+2nd moments of edge features ----------------
__global__ void k2_mom() {
    int t = blockIdx.x*blockDim.x + threadIdx.x;     // 512x256 -> 5 samples each
    float s1[6]; float s2[21];
    #pragma unroll
    for (int c = 0; c < 6; c++)  s1[c] = 0.f;
    #pragma unroll
    for (int q = 0; q < 21; q++) s2[q] = 0.f;

    #pragma unroll
    for (int s = 0; s < 5; s++) {
        size_t idx = (size_t)(t*5 + s) * 8;
        float4 v0 = *(const float4*)&g_E8[idx];
        float4 v1 = *(const float4*)&g_E8[idx+4];
        float x[6] = {v0.x, v0.y, v0.z, v0.w, v1.x, v1.y};
        #pragma unroll
        for (int c = 0; c < 6; c++) s1[c] += x[c];
        int q = 0;
        #pragma unroll
        for (int c1 = 0; c1 < 6; c1++)
            #pragma unroll
            for (int c2 = c1; c2 < 6; c2++) { s2[q] = fmaf(x[c1], x[c2], s2[q]); q++; }
    }
    #pragma unroll
    for (int o = 16; o > 0; o >>= 1) {
        #pragma unroll
        for (int c = 0; c < 6; c++)  s1[c] += __shfl_xor_sync(~0u, s1[c], o);
        #pragma unroll
        for (int q = 0; q < 21; q++) s2[q] += __shfl_xor_sync(~0u, s2[q], o);
    }
    if ((threadIdx.x & 31) == 0) {
        #pragma unroll
        for (int c = 0; c < 6; c++)  atomicAdd(&g_S1[c], (double)s1[c]);
        #pragma unroll
        for (int q = 0; q < 21; q++) atomicAdd(&g_S2[q], (double)s2[q]);
    }
}

// ---------------- F1: fold BN1 into W1 ----------------
__global__ void f1_fold(const float* __restrict__ W1, const float* __restrict__ g1,
                        const float* __restrict__ b1) {
    int o = threadIdx.x; if (o >= CH) return;
    double M = (double)NSAMP;
    double m1[6];
    for (int c = 0; c < 6; c++) m1[c] = g_S1[c] / M;
    double E2[6][6]; int q = 0;
    for (int c1 = 0; c1 < 6; c1++)
        for (int c2 = c1; c2 < 6; c2++) { double v = g_S2[q++] / M; E2[c1][c2] = v; E2[c2][c1] = v; }
    double w[6];
    for (int c = 0; c < 6; c++) w[c] = (double)W1[o*6 + c];
    double mean = 0.0;
    for (int c = 0; c < 6; c++) mean += w[c]*m1[c];
    double e2 = 0.0;
    for (int c1 = 0; c1 < 6; c1++) { double acc = 0.0;
        for (int c2 = 0; c2 < 6; c2++) acc += w[c2]*E2[c1][c2];
        e2 += w[c1]*acc; }
    double var = e2 - mean*mean;
    double a = (double)g1[o] / sqrt(var + BN_EPS);
    g_c1[o] = (float)((double)b1[o] - mean*a);
    for (int c = 0; c < 6; c++) g_W1f[o*6 + c] = (float)(a*w[c]);
}

// ---------------- K3: fused MLP (f32x2 packed), BN2 stats, max/min over K
#define YPITCH 22
__global__ void __launch_bounds__(256) k3_mlp(const float* __restrict__ W2) {
    __shared__ float sW2T[CH*CH];          // [c][u]
    __shared__ float y1s[4][CH*YPITCH];    // [p][c*22 + k]
    __shared__ float smx[4][CH], smn[4][CH];
    __shared__ float ssum[CH], ssq[CH];
    int t = threadIdx.x;
    if (t < CH) { ssum[t] = 0.f; ssq[t] = 0.f; }
    for (int s = t; s < CH*CH; s += 256) { int o = s >> 6, c = s & 63; sW2T[c*CH + o] = W2[s]; }

    int pa = t >> 6, ca = t & 63;
    float w1r[6];
    #pragma unroll
    for (int c = 0; c < 6; c++) w1r[c] = g_W1f[ca*6 + c];
    float c1v = g_c1[ca];

    int r  = t & 63;
    int kq = r >> 5;
    int ug = r & 31;
    int u0 = 2*ug, u1 = u0 + 1;
    int k0 = kq * 10;
    float su0 = 0.f, su1 = 0.f, qu0 = 0.f, qu1 = 0.f;
    __syncthreads();

    for (int ph = 0; ph < 4; ph++) {
        int pbase = blockIdx.x*16 + ph*4;
        {
            const float* Ep = g_E8 + (size_t)(pbase + pa)*KNN*8;
            float* yo = &y1s[pa][ca*YPITCH];
            #pragma unroll
            for (int k = 0; k < KNN; k++) {
                float4 v0 = *(const float4*)(Ep + k*8);
                float4 v1 = *(const float4*)(Ep + k*8 + 4);
                float h = c1v;
                h = fmaf(w1r[0], v0.x, h);
                h = fmaf(w1r[1], v0.y, h);
                h = fmaf(w1r[2], v0.z, h);
                h = fmaf(w1r[3], v0.w, h);
                h = fmaf(w1r[4], v1.x, h);
                h = fmaf(w1r[5], v1.y, h);
                yo[k] = (h >= 0.f) ? h : SLOPE*h;
            }
        }
        __syncthreads();
        unsigned long long acc0[5], acc1[5];
        #pragma unroll
        for (int kk = 0; kk < 5; kk++) { acc0[kk] = 0ull; acc1[kk] = 0ull; }
        const float* yb = &y1s[pa][0];
        #pragma unroll 8
        for (int c = 0; c < CH; c++) {
            float2 wp = *(const float2*)&sW2T[c*CH + u0];
            unsigned long long w0d = pack2(wp.x);
            unsigned long long w1d = pack2(wp.y);
            const float* yr = yb + c*YPITCH + k0;
            #pragma unroll
            for (int kk = 0; kk < 5; kk++) {
                unsigned long long yv = *(const unsigned long long*)(yr + 2*kk);
                acc0[kk] = fma2(w0d, yv, acc0[kk]);
                acc1[kk] = fma2(w1d, yv, acc1[kk]);
            }
        }
        float mx0 = -CUDART_INF_F, mn0 = CUDART_INF_F;
        float mx1 = -CUDART_INF_F, mn1 = CUDART_INF_F;
        #pragma unroll
        for (int kk = 0; kk < 5; kk++) {
            float lo, hi;
            unpack2(acc0[kk], lo, hi);
            su0 += lo + hi; qu0 = fmaf(lo, lo, fmaf(hi, hi, qu0));
            mx0 = fmaxf(mx0, fmaxf(lo, hi)); mn0 = fminf(mn0, fminf(lo, hi));
            unpack2(acc1[kk], lo, hi);
            su1 += lo + hi; qu1 = fmaf(lo, lo, fmaf(hi, hi, qu1));
            mx1 = fmaxf(mx1, fmaxf(lo, hi)); mn1 = fminf(mn1, fminf(lo, hi));
        }
        if (kq == 1) {
            smx[pa][u0] = mx0; smx[pa][u1] = mx1;
            smn[pa][u0] = mn0; smn[pa][u1] = mn1;
        }
        __syncthreads();
        if (kq == 0) {
            size_t o = (size_t)(pbase + pa)*CH;
            g_hmax[o + u0] = fmaxf(mx0, smx[pa][u0]);
            g_hmax[o + u1] = fmaxf(mx1, smx[pa][u1]);
            g_hmin[o + u0] = fminf(mn0, smn[pa][u0]);
            g_hmin[o + u1] = fminf(mn1, smn[pa][u1]);
        }
        __syncthreads();
    }
    atomicAdd(&ssum[u0], su0); atomicAdd(&ssum[u1], su1);
    atomicAdd(&ssq[u0],  qu0); atomicAdd(&ssq[u1],  qu1);
    __syncthreads();
    if (t < CH) {
        atomicAdd(&g_h2sum[t], (double)ssum[t]);
        atomicAdd(&g_h2sq[t],  (double)ssq[t]);
    }
}

// ---------------- F2: finalize BN2 ----------------
__global__ void f2_fold(const float* __restrict__ g2, const float* __restrict__ b2) {
    int o = threadIdx.x; if (o >= CH) return;
    double M = (double)NSAMP;
    double m = g_h2sum[o] / M;
    double v = g_h2sq[o] / M - m*m;
    double a = (double)g2[o] / sqrt(v + BN_EPS);
    g_a2[o] = (float)a;
    g_c2[o] = (float)((double)b2[o] - m*a);
}

// ---------------- K5: BN2+lrelu via monotone max/min + transpose -------
__global__ void k5_out(float* __restrict__ out) {
    __shared__ float tile[32][33];
    int b = blockIdx.z;
    int n0 = blockIdx.x*32, o0 = blockIdx.y*32;
    int tx = threadIdx.x, ty = threadIdx.y;
    #pragma unroll
    for (int r = 0; r < 4; r++) {
        int n = n0 + ty + 8*r, o = o0 + tx;
        float a = g_a2[o], c = g_c2[o];
        size_t idx = ((size_t)(b*NPTS + n))*CH + o;
        float h = (a >= 0.f) ? g_hmax[idx] : g_hmin[idx];
        float v = fmaf(a, h, c);
        tile[ty + 8*r][tx] = (v >= 0.f) ? v : SLOPE*v;
    }
    __syncthreads();
    #pragma unroll
    for (int r = 0; r < 4; r++) {
        int o = o0 + ty + 8*r, n = n0 + tx;
        out[((size_t)(b*CH + o))*NPTS + n] = tile[tx][ty + 8*r];
    }
}

// ---------------- launch ----------------
extern "C" void kernel_launch(void* const* d_in, const int* in_sizes, int n_in,
                              void* d_out, int out_size) {
    const float* a  = (const float*)d_in[0];
    const float* W1 = (const float*)d_in[1];
    const float* g1 = (const float*)d_in[2];
    const float* b1 = (const float*)d_in[3];
    const float* W2 = (const float*)d_in[4];
    const float* g2 = (const float*)d_in[5];
    const float* b2 = (const float*)d_in[6];
    float* out = (float*)d_out;

    // 1 dummy: ncu capture lands on launch index 3 == k1_emit
    kdummy<<<1, 32>>>();

    k0_pack<<<128, 256>>>(a);        // index 1
    k1_seg<<<512, 128>>>();          // index 2
    k1_emit<<<4096, 256>>>();        // index 3  <- profiled
    k2_mom<<<512, 256>>>();
    f1_fold<<<1, 64>>>(W1, g1, b1);
    k3_mlp<<<2048, 256>>>(W2);
    f2_fold<<<1, 64>>>(g2, b2);
    k5_out<<<dim3(128, 2, NB), dim3(32, 8)>>>(out);
}